// round 3
// baseline (speedup 1.0000x reference)
#include <cuda_runtime.h>
#include <cuda_bf16.h>
#include <cstdint>

#define N_NODES 50000
#define N_EDGES 800000
#define IN_DIM  256
#define HC      128   // HEADS * OUT_DIM
#define HEADS   4
#define NEG_SLOPE 0.2f
#define LN_EPS  1e-5f

// Scratch (static device globals; no allocation at runtime)
__device__ float g_h[(size_t)N_NODES * HC];      // transformed features [N,128]
__device__ float g_acc[(size_t)N_NODES * HC];    // weighted message accumulator
__device__ float g_as[N_NODES * HEADS];          // alpha_src per node/head
__device__ float g_ad[N_NODES * HEADS];          // alpha_dst per node/head
__device__ float g_denom[N_NODES * HEADS];       // softmax denominator

// ---------------------------------------------------------------------------
// tf32 split: v = hi + lo, both tf32-rounded (3xTF32 scheme, fp32-accurate)
// ---------------------------------------------------------------------------
__device__ __forceinline__ float2 tf32_split(float v) {
    uint32_t hu;
    asm("cvt.rna.tf32.f32 %0, %1;" : "=r"(hu) : "f"(v));
    float hi = __uint_as_float(hu);
    float r  = v - hi;
    uint32_t lu;
    asm("cvt.rna.tf32.f32 %0, %1;" : "=r"(lu) : "f"(r));
    return make_float2(hi, __uint_as_float(lu));
}

#define MMA_TF32(D, A0, A1, A2, A3, B0, B1)                                   \
    asm volatile(                                                             \
        "mma.sync.aligned.m16n8k8.row.col.f32.tf32.tf32.f32 "                 \
        "{%0,%1,%2,%3},{%4,%5,%6,%7},{%8,%9},{%0,%1,%2,%3};"                  \
        : "+f"(D[0]), "+f"(D[1]), "+f"(D[2]), "+f"(D[3])                      \
        : "r"(A0), "r"(A1), "r"(A2), "r"(A3), "r"(B0), "r"(B1))

// ---------------------------------------------------------------------------
// K1: h = x @ W via 3xTF32 tensor-core mma, fused with per-node attention
// logits (a_s, a_d) and self-loop init of denom/acc.
// Block: 256 thr (8 warps). Tile: M=128 (16 rows/warp), N=128 full, K chunks 16.
// ---------------------------------------------------------------------------
__global__ __launch_bounds__(256) void gemm_mma_k(const float* __restrict__ x,
                                                  const float* __restrict__ W,
                                                  const float* __restrict__ att_src,
                                                  const float* __restrict__ att_dst) {
    // float2 = (hi, lo). Strides chosen ≡ 4 (mod 16) in float2 units for
    // conflict-free quad fragment loads.
    __shared__ float2 Xs2[128][20];   // [node-in-tile][k-in-chunk]  20.5 KB
    __shared__ float2 Ws2[16][132];   // [k-in-chunk][col]           16.9 KB
    __shared__ float  s_as[HC], s_ad[HC];

    const int tid  = threadIdx.x;
    const int warp = tid >> 5;
    const int lane = tid & 31;
    const int g    = lane >> 2;    // group id (row within m16)
    const int tig  = lane & 3;     // thread in group
    const int nb   = blockIdx.x * 128;

    if (tid < HC) { s_as[tid] = att_src[tid]; s_ad[tid] = att_dst[tid]; }

    float d[16][4];
#pragma unroll
    for (int nt = 0; nt < 16; nt++)
#pragma unroll
        for (int c = 0; c < 4; c++) d[nt][c] = 0.f;

    for (int kc = 0; kc < IN_DIM; kc += 16) {
        // --- load X chunk: 128 rows x 16 k (512 float4, 2/thread) ---
#pragma unroll
        for (int i = 0; i < 2; i++) {
            int idx = tid + i * 256;
            int row = idx >> 2, q = idx & 3;
            int gn  = nb + row; if (gn > N_NODES - 1) gn = N_NODES - 1;
            float4 v = *(const float4*)(x + (size_t)gn * IN_DIM + kc + q * 4);
            Xs2[row][q * 4 + 0] = tf32_split(v.x);
            Xs2[row][q * 4 + 1] = tf32_split(v.y);
            Xs2[row][q * 4 + 2] = tf32_split(v.z);
            Xs2[row][q * 4 + 3] = tf32_split(v.w);
        }
        // --- load W chunk: 16 rows x 128 cols (512 float4, 2/thread) ---
#pragma unroll
        for (int i = 0; i < 2; i++) {
            int idx = tid + i * 256;
            int row = idx >> 5, q = idx & 31;
            float4 v = *(const float4*)(W + (size_t)(kc + row) * HC + q * 4);
            Ws2[row][q * 4 + 0] = tf32_split(v.x);
            Ws2[row][q * 4 + 1] = tf32_split(v.y);
            Ws2[row][q * 4 + 2] = tf32_split(v.z);
            Ws2[row][q * 4 + 3] = tf32_split(v.w);
        }
        __syncthreads();

#pragma unroll
        for (int ks = 0; ks < 2; ks++) {
            const int k0 = ks * 8;
            const int r0 = warp * 16 + g;
            float2 A0 = Xs2[r0    ][k0 + tig];
            float2 A1 = Xs2[r0 + 8][k0 + tig];
            float2 A2 = Xs2[r0    ][k0 + tig + 4];
            float2 A3 = Xs2[r0 + 8][k0 + tig + 4];
            uint32_t a0h = __float_as_uint(A0.x), a0l = __float_as_uint(A0.y);
            uint32_t a1h = __float_as_uint(A1.x), a1l = __float_as_uint(A1.y);
            uint32_t a2h = __float_as_uint(A2.x), a2l = __float_as_uint(A2.y);
            uint32_t a3h = __float_as_uint(A3.x), a3l = __float_as_uint(A3.y);
#pragma unroll
            for (int nt = 0; nt < 16; nt++) {
                float2 B0 = Ws2[k0 + tig    ][nt * 8 + g];
                float2 B1 = Ws2[k0 + tig + 4][nt * 8 + g];
                uint32_t b0h = __float_as_uint(B0.x), b0l = __float_as_uint(B0.y);
                uint32_t b1h = __float_as_uint(B1.x), b1l = __float_as_uint(B1.y);
                MMA_TF32(d[nt], a0h, a1h, a2h, a3h, b0h, b1h);  // hi*hi
                MMA_TF32(d[nt], a0h, a1h, a2h, a3h, b0l, b1l);  // hi*lo
                MMA_TF32(d[nt], a0l, a1l, a2l, a3l, b0h, b1h);  // lo*hi
            }
        }
        __syncthreads();
    }

    // ---- fused epilogue: attention logits + self-loop init + stores ----
    // d[nt][0],[1]: row_l = nb+warp*16+g,   cols nt*8+2*tig, +1
    // d[nt][2],[3]: row_h = row_l + 8
    const int rl = warp * 16 + g;
    const int n_l = nb + rl, n_h = nb + rl + 8;

    float ps_l[HEADS], pd_l[HEADS], ps_h[HEADS], pd_h[HEADS];
#pragma unroll
    for (int h = 0; h < HEADS; h++) { ps_l[h]=pd_l[h]=ps_h[h]=pd_h[h]=0.f; }
#pragma unroll
    for (int nt = 0; nt < 16; nt++) {
        int h  = nt >> 2;
        int c0 = nt * 8 + tig * 2;
        float as0 = s_as[c0], as1 = s_as[c0 + 1];
        float ad0 = s_ad[c0], ad1 = s_ad[c0 + 1];
        ps_l[h] += d[nt][0] * as0 + d[nt][1] * as1;
        pd_l[h] += d[nt][0] * ad0 + d[nt][1] * ad1;
        ps_h[h] += d[nt][2] * as0 + d[nt][3] * as1;
        pd_h[h] += d[nt][2] * ad0 + d[nt][3] * ad1;
    }
#pragma unroll
    for (int h = 0; h < HEADS; h++) {
#pragma unroll
        for (int o = 1; o <= 2; o <<= 1) {
            ps_l[h] += __shfl_xor_sync(0xffffffffu, ps_l[h], o);
            pd_l[h] += __shfl_xor_sync(0xffffffffu, pd_l[h], o);
            ps_h[h] += __shfl_xor_sync(0xffffffffu, ps_h[h], o);
            pd_h[h] += __shfl_xor_sync(0xffffffffu, pd_h[h], o);
        }
    }
    float wl[HEADS], wh[HEADS];
#pragma unroll
    for (int h = 0; h < HEADS; h++) {
        float zl = ps_l[h] + pd_l[h];
        float zh = ps_h[h] + pd_h[h];
        wl[h] = __expf(zl > 0.f ? zl : NEG_SLOPE * zl);
        wh[h] = __expf(zh > 0.f ? zh : NEG_SLOPE * zh);
    }

    if (n_l < N_NODES) {
#pragma unroll
        for (int nt = 0; nt < 16; nt++) {
            int h = nt >> 2, c0 = nt * 8 + tig * 2;
            *(float2*)(g_h   + (size_t)n_l * HC + c0) = make_float2(d[nt][0], d[nt][1]);
            *(float2*)(g_acc + (size_t)n_l * HC + c0) =
                make_float2(wl[h] * d[nt][0], wl[h] * d[nt][1]);
        }
        if (tig == 0) {
#pragma unroll
            for (int h = 0; h < HEADS; h++) {
                g_as[n_l * HEADS + h]    = ps_l[h];
                g_ad[n_l * HEADS + h]    = pd_l[h];
                g_denom[n_l * HEADS + h] = wl[h];
            }
        }
    }
    if (n_h < N_NODES) {
#pragma unroll
        for (int nt = 0; nt < 16; nt++) {
            int h = nt >> 2, c0 = nt * 8 + tig * 2;
            *(float2*)(g_h   + (size_t)n_h * HC + c0) = make_float2(d[nt][2], d[nt][3]);
            *(float2*)(g_acc + (size_t)n_h * HC + c0) =
                make_float2(wh[h] * d[nt][2], wh[h] * d[nt][3]);
        }
        if (tig == 0) {
#pragma unroll
            for (int h = 0; h < HEADS; h++) {
                g_as[n_h * HEADS + h]    = ps_h[h];
                g_ad[n_h * HEADS + h]    = pd_h[h];
                g_denom[n_h * HEADS + h] = wh[h];
            }
        }
    }
}

// ---------------------------------------------------------------------------
// K3: edge scatter. One warp per edge.
//   w = exp(leaky(a_s[src,h] + a_d[dst,h]))
//   denom[dst,h] += w ;  acc[dst, :] += w * h[src, :]
// Uses red.global.add.v4.f32 for the 128-channel scatter.
// ---------------------------------------------------------------------------
__global__ __launch_bounds__(256) void edge_k(const int* __restrict__ ei) {
    int gt   = blockIdx.x * 256 + threadIdx.x;
    int e    = gt >> 5;
    int lane = gt & 31;
    if (e >= N_EDGES) return;

    int s = __ldg(ei + e);
    int d = __ldg(ei + N_EDGES + e);

    float4 hv = __ldg((const float4*)(g_h + (size_t)s * HC) + lane);
    int head  = lane >> 3;
    float as  = __ldg(g_as + s * HEADS + head);
    float ad  = __ldg(g_ad + d * HEADS + head);
    float z   = as + ad;
    float le  = z > 0.f ? z : NEG_SLOPE * z;
    float w   = __expf(le);

    if ((lane & 7) == 0) atomicAdd(g_denom + d * HEADS + head, w);

    float* p = g_acc + (size_t)d * HC + lane * 4;
    asm volatile("red.global.add.v4.f32 [%0], {%1,%2,%3,%4};" ::
                 "l"(p), "f"(w * hv.x), "f"(w * hv.y),
                 "f"(w * hv.z), "f"(w * hv.w)
                 : "memory");
}

// ---------------------------------------------------------------------------
// K4: finalize: out = ELU( LN( acc/denom + bias ) * gamma + beta )
// One warp per node (128 channels, 4 per lane).
// ---------------------------------------------------------------------------
__global__ __launch_bounds__(256) void final_k(const float* __restrict__ bias,
                                               const float* __restrict__ gamma,
                                               const float* __restrict__ beta,
                                               float* __restrict__ out) {
    int gt   = blockIdx.x * 256 + threadIdx.x;
    int n    = gt >> 5;
    int lane = gt & 31;
    if (n >= N_NODES) return;

    float4 a  = *(const float4*)(g_acc + (size_t)n * HC + lane * 4);
    int head  = lane >> 3;
    float inv = 1.0f / g_denom[n * HEADS + head];
    float4 b4 = *(const float4*)(bias + lane * 4);

    float v0 = a.x * inv + b4.x;
    float v1 = a.y * inv + b4.y;
    float v2 = a.z * inv + b4.z;
    float v3 = a.w * inv + b4.w;

    float s = v0 + v1 + v2 + v3;
#pragma unroll
    for (int o = 16; o >= 1; o >>= 1) s += __shfl_xor_sync(0xffffffffu, s, o);
    float mean = s * (1.0f / 128.0f);

    float d0 = v0 - mean, d1 = v1 - mean, d2 = v2 - mean, d3 = v3 - mean;
    float q = d0 * d0 + d1 * d1 + d2 * d2 + d3 * d3;
#pragma unroll
    for (int o = 16; o >= 1; o >>= 1) q += __shfl_xor_sync(0xffffffffu, q, o);
    float r = rsqrtf(q * (1.0f / 128.0f) + LN_EPS);

    float4 g4  = *(const float4*)(gamma + lane * 4);
    float4 be4 = *(const float4*)(beta + lane * 4);
    float o0 = d0 * r * g4.x + be4.x;
    float o1 = d1 * r * g4.y + be4.y;
    float o2 = d2 * r * g4.z + be4.z;
    float o3 = d3 * r * g4.w + be4.w;
    // ELU (alpha = 1)
    o0 = o0 > 0.f ? o0 : (expf(o0) - 1.0f);
    o1 = o1 > 0.f ? o1 : (expf(o1) - 1.0f);
    o2 = o2 > 0.f ? o2 : (expf(o2) - 1.0f);
    o3 = o3 > 0.f ? o3 : (expf(o3) - 1.0f);

    *(float4*)(out + (size_t)n * HC + lane * 4) = make_float4(o0, o1, o2, o3);
}

// ---------------------------------------------------------------------------
extern "C" void kernel_launch(void* const* d_in, const int* in_sizes, int n_in,
                              void* d_out, int out_size) {
    const float* x       = (const float*)d_in[0];
    const int*   ei      = (const int*)d_in[1];
    const float* W       = (const float*)d_in[2];
    const float* att_src = (const float*)d_in[3];
    const float* att_dst = (const float*)d_in[4];
    const float* bias    = (const float*)d_in[5];
    const float* gamma   = (const float*)d_in[6];
    const float* beta    = (const float*)d_in[7];
    float*       out     = (float*)d_out;

    gemm_mma_k<<<(N_NODES + 127) / 128, 256>>>(x, W, att_src, att_dst);
    edge_k<<<(N_EDGES + 7) / 8, 256>>>(ei);          // 1 warp / edge
    final_k<<<(N_NODES * 32 + 255) / 256, 256>>>(bias, gamma, beta, out);
}

// round 4
// speedup vs baseline: 1.2782x; 1.2782x over previous
#include <cuda_runtime.h>
#include <cuda_bf16.h>
#include <cstdint>

#define N_NODES 50000
#define N_EDGES 800000
#define IN_DIM  256
#define HC      128   // HEADS * OUT_DIM
#define HEADS   4
#define NEG_SLOPE 0.2f
#define LN_EPS  1e-5f

// Scratch (static device globals; no allocation at runtime)
__device__ float g_h[(size_t)N_NODES * HC];      // transformed features [N,128]
__device__ float g_as[N_NODES * HEADS];          // alpha_src per node/head
__device__ float g_ad[N_NODES * HEADS];          // alpha_dst per node/head
// CSR-by-dst scratch
__device__ int   g_deg[N_NODES];                 // in-degree histogram
__device__ int   g_cur[N_NODES];                 // fill cursors
__device__ int   g_row[N_NODES + 1];             // row pointers (exclusive scan)
__device__ int   g_col[N_EDGES];                 // src id per CSR slot
__device__ int   g_scan[50176];                  // block-local inclusive scans
__device__ int   g_poff[64];                     // per-block exclusive offsets

// ---------------------------------------------------------------------------
// tf32 split: v = hi + lo, both tf32-rounded (3xTF32 scheme, fp32-accurate)
// ---------------------------------------------------------------------------
__device__ __forceinline__ float2 tf32_split(float v) {
    uint32_t hu;
    asm("cvt.rna.tf32.f32 %0, %1;" : "=r"(hu) : "f"(v));
    float hi = __uint_as_float(hu);
    float r  = v - hi;
    uint32_t lu;
    asm("cvt.rna.tf32.f32 %0, %1;" : "=r"(lu) : "f"(r));
    return make_float2(hi, __uint_as_float(lu));
}

#define MMA_TF32(D, A0, A1, A2, A3, B0, B1)                                   \
    asm volatile(                                                             \
        "mma.sync.aligned.m16n8k8.row.col.f32.tf32.tf32.f32 "                 \
        "{%0,%1,%2,%3},{%4,%5,%6,%7},{%8,%9},{%0,%1,%2,%3};"                  \
        : "+f"(D[0]), "+f"(D[1]), "+f"(D[2]), "+f"(D[3])                      \
        : "r"(A0), "r"(A1), "r"(A2), "r"(A3), "r"(B0), "r"(B1))

// ---------------------------------------------------------------------------
// K1: h = x @ W via 3xTF32 tensor-core mma, fused with attention logits.
// ---------------------------------------------------------------------------
__global__ __launch_bounds__(256) void gemm_mma_k(const float* __restrict__ x,
                                                  const float* __restrict__ W,
                                                  const float* __restrict__ att_src,
                                                  const float* __restrict__ att_dst) {
    __shared__ float2 Xs2[128][20];   // (hi,lo) pairs
    __shared__ float2 Ws2[16][132];
    __shared__ float  s_as[HC], s_ad[HC];

    const int tid  = threadIdx.x;
    const int warp = tid >> 5;
    const int lane = tid & 31;
    const int g    = lane >> 2;
    const int tig  = lane & 3;
    const int nb   = blockIdx.x * 128;

    if (tid < HC) { s_as[tid] = att_src[tid]; s_ad[tid] = att_dst[tid]; }

    float d[16][4];
#pragma unroll
    for (int nt = 0; nt < 16; nt++)
#pragma unroll
        for (int c = 0; c < 4; c++) d[nt][c] = 0.f;

    for (int kc = 0; kc < IN_DIM; kc += 16) {
#pragma unroll
        for (int i = 0; i < 2; i++) {
            int idx = tid + i * 256;
            int row = idx >> 2, q = idx & 3;
            int gn  = nb + row; if (gn > N_NODES - 1) gn = N_NODES - 1;
            float4 v = *(const float4*)(x + (size_t)gn * IN_DIM + kc + q * 4);
            Xs2[row][q * 4 + 0] = tf32_split(v.x);
            Xs2[row][q * 4 + 1] = tf32_split(v.y);
            Xs2[row][q * 4 + 2] = tf32_split(v.z);
            Xs2[row][q * 4 + 3] = tf32_split(v.w);
        }
#pragma unroll
        for (int i = 0; i < 2; i++) {
            int idx = tid + i * 256;
            int row = idx >> 5, q = idx & 31;
            float4 v = *(const float4*)(W + (size_t)(kc + row) * HC + q * 4);
            Ws2[row][q * 4 + 0] = tf32_split(v.x);
            Ws2[row][q * 4 + 1] = tf32_split(v.y);
            Ws2[row][q * 4 + 2] = tf32_split(v.z);
            Ws2[row][q * 4 + 3] = tf32_split(v.w);
        }
        __syncthreads();

#pragma unroll
        for (int ks = 0; ks < 2; ks++) {
            const int k0 = ks * 8;
            const int r0 = warp * 16 + g;
            float2 A0 = Xs2[r0    ][k0 + tig];
            float2 A1 = Xs2[r0 + 8][k0 + tig];
            float2 A2 = Xs2[r0    ][k0 + tig + 4];
            float2 A3 = Xs2[r0 + 8][k0 + tig + 4];
            uint32_t a0h = __float_as_uint(A0.x), a0l = __float_as_uint(A0.y);
            uint32_t a1h = __float_as_uint(A1.x), a1l = __float_as_uint(A1.y);
            uint32_t a2h = __float_as_uint(A2.x), a2l = __float_as_uint(A2.y);
            uint32_t a3h = __float_as_uint(A3.x), a3l = __float_as_uint(A3.y);
#pragma unroll
            for (int nt = 0; nt < 16; nt++) {
                float2 B0 = Ws2[k0 + tig    ][nt * 8 + g];
                float2 B1 = Ws2[k0 + tig + 4][nt * 8 + g];
                uint32_t b0h = __float_as_uint(B0.x), b0l = __float_as_uint(B0.y);
                uint32_t b1h = __float_as_uint(B1.x), b1l = __float_as_uint(B1.y);
                MMA_TF32(d[nt], a0h, a1h, a2h, a3h, b0h, b1h);
                MMA_TF32(d[nt], a0h, a1h, a2h, a3h, b0l, b1l);
                MMA_TF32(d[nt], a0l, a1l, a2l, a3l, b0h, b1h);
            }
        }
        __syncthreads();
    }

    // ---- epilogue: store h, compute + store attention logits ----
    const int rl = warp * 16 + g;
    const int n_l = nb + rl, n_h = nb + rl + 8;

    float ps_l[HEADS], pd_l[HEADS], ps_h[HEADS], pd_h[HEADS];
#pragma unroll
    for (int h = 0; h < HEADS; h++) { ps_l[h]=pd_l[h]=ps_h[h]=pd_h[h]=0.f; }
#pragma unroll
    for (int nt = 0; nt < 16; nt++) {
        int h  = nt >> 2;
        int c0 = nt * 8 + tig * 2;
        float as0 = s_as[c0], as1 = s_as[c0 + 1];
        float ad0 = s_ad[c0], ad1 = s_ad[c0 + 1];
        ps_l[h] += d[nt][0] * as0 + d[nt][1] * as1;
        pd_l[h] += d[nt][0] * ad0 + d[nt][1] * ad1;
        ps_h[h] += d[nt][2] * as0 + d[nt][3] * as1;
        pd_h[h] += d[nt][2] * ad0 + d[nt][3] * ad1;
    }
#pragma unroll
    for (int h = 0; h < HEADS; h++) {
#pragma unroll
        for (int o = 1; o <= 2; o <<= 1) {
            ps_l[h] += __shfl_xor_sync(0xffffffffu, ps_l[h], o);
            pd_l[h] += __shfl_xor_sync(0xffffffffu, pd_l[h], o);
            ps_h[h] += __shfl_xor_sync(0xffffffffu, ps_h[h], o);
            pd_h[h] += __shfl_xor_sync(0xffffffffu, pd_h[h], o);
        }
    }
    if (n_l < N_NODES) {
#pragma unroll
        for (int nt = 0; nt < 16; nt++) {
            int c0 = nt * 8 + tig * 2;
            *(float2*)(g_h + (size_t)n_l * HC + c0) = make_float2(d[nt][0], d[nt][1]);
        }
        if (tig == 0)
#pragma unroll
            for (int h = 0; h < HEADS; h++) {
                g_as[n_l * HEADS + h] = ps_l[h];
                g_ad[n_l * HEADS + h] = pd_l[h];
            }
    }
    if (n_h < N_NODES) {
#pragma unroll
        for (int nt = 0; nt < 16; nt++) {
            int c0 = nt * 8 + tig * 2;
            *(float2*)(g_h + (size_t)n_h * HC + c0) = make_float2(d[nt][2], d[nt][3]);
        }
        if (tig == 0)
#pragma unroll
            for (int h = 0; h < HEADS; h++) {
                g_as[n_h * HEADS + h] = ps_h[h];
                g_ad[n_h * HEADS + h] = pd_h[h];
            }
    }
}

// ---------------------------------------------------------------------------
// CSR build: zero -> hist -> scan (2-level) -> fill
// ---------------------------------------------------------------------------
__global__ __launch_bounds__(256) void zero_k() {
    int i = blockIdx.x * 256 + threadIdx.x;
    if (i < N_NODES) { g_deg[i] = 0; g_cur[i] = 0; }
}

__global__ __launch_bounds__(256) void hist_k(const int* __restrict__ ei) {
    int e = blockIdx.x * 256 + threadIdx.x;
    if (e < N_EDGES) atomicAdd(&g_deg[__ldg(ei + N_EDGES + e)], 1);
}

// 49 blocks x 1024: block-local inclusive scan
__global__ __launch_bounds__(1024) void scan1_k() {
    __shared__ int s[1024];
    int tid = threadIdx.x;
    int i   = blockIdx.x * 1024 + tid;
    int v   = (i < N_NODES) ? g_deg[i] : 0;
    s[tid] = v;
    __syncthreads();
#pragma unroll
    for (int off = 1; off < 1024; off <<= 1) {
        int t = (tid >= off) ? s[tid - off] : 0;
        __syncthreads();
        s[tid] += t;
        __syncthreads();
    }
    g_scan[i] = s[tid];
    if (tid == 1023) g_poff[blockIdx.x] = s[1023];   // block totals (temp)
}

// 1 block: exclusive-scan the 49 block totals in place
__global__ __launch_bounds__(64) void scan2_k(int nblk) {
    __shared__ int s[64];
    int tid = threadIdx.x;
    s[tid] = (tid < nblk) ? g_poff[tid] : 0;
    __syncthreads();
    if (tid == 0) {
        int run = 0;
        for (int b = 0; b < nblk; b++) { int t = s[b]; s[b] = run; run += t; }
    }
    __syncthreads();
    if (tid < nblk) g_poff[tid] = s[tid];
}

__global__ __launch_bounds__(256) void scan3_k() {
    int i = blockIdx.x * 256 + threadIdx.x;
    if (i < N_NODES) g_row[i + 1] = g_scan[i] + g_poff[i >> 10];
    if (i == 0) g_row[0] = 0;
}

__global__ __launch_bounds__(256) void fill_k(const int* __restrict__ ei) {
    int e = blockIdx.x * 256 + threadIdx.x;
    if (e >= N_EDGES) return;
    int s = __ldg(ei + e);
    int d = __ldg(ei + N_EDGES + e);
    int pos = g_row[d] + atomicAdd(&g_cur[d], 1);
    g_col[pos] = s;
}

// ---------------------------------------------------------------------------
// Aggregation (gather-only) fused with LayerNorm + ELU.
// One warp per dst node; lane owns 4 channels; head = lane>>3.
// ---------------------------------------------------------------------------
__global__ __launch_bounds__(256) void aggr_k(const float* __restrict__ bias,
                                              const float* __restrict__ gamma,
                                              const float* __restrict__ beta,
                                              float* __restrict__ out) {
    int gt   = blockIdx.x * 256 + threadIdx.x;
    int n    = gt >> 5;
    int lane = gt & 31;
    if (n >= N_NODES) return;
    int head = lane >> 3;

    float ad_n = __ldg(g_ad + n * HEADS + head);

    // self-loop initializes the accumulator
    float as_s = __ldg(g_as + n * HEADS + head);
    float z    = as_s + ad_n;
    float w    = __expf(z > 0.f ? z : NEG_SLOPE * z);
    float4 hv  = __ldg((const float4*)(g_h + (size_t)n * HC) + lane);
    float a0 = w * hv.x, a1 = w * hv.y, a2 = w * hv.z, a3 = w * hv.w;
    float den = w;

    int e0 = __ldg(g_row + n), e1 = __ldg(g_row + n + 1);
    int s_next = (e0 < e1) ? __ldg(g_col + e0) : 0;
    for (int i = e0; i < e1; i++) {
        int s = s_next;
        if (i + 1 < e1) s_next = __ldg(g_col + i + 1);
        float4 h4 = __ldg((const float4*)(g_h + (size_t)s * HC) + lane);
        float as  = __ldg(g_as + s * HEADS + head);
        float zz  = as + ad_n;
        float ww  = __expf(zz > 0.f ? zz : NEG_SLOPE * zz);
        a0 = fmaf(ww, h4.x, a0);
        a1 = fmaf(ww, h4.y, a1);
        a2 = fmaf(ww, h4.z, a2);
        a3 = fmaf(ww, h4.w, a3);
        den += ww;
    }

    // out_pre = acc/den + bias, then LayerNorm + ELU
    float inv = 1.0f / den;
    float4 b4 = __ldg((const float4*)bias + lane);
    float v0 = a0 * inv + b4.x;
    float v1 = a1 * inv + b4.y;
    float v2 = a2 * inv + b4.z;
    float v3 = a3 * inv + b4.w;

    float s = v0 + v1 + v2 + v3;
#pragma unroll
    for (int o = 16; o >= 1; o >>= 1) s += __shfl_xor_sync(0xffffffffu, s, o);
    float mean = s * (1.0f / 128.0f);

    float d0 = v0 - mean, d1 = v1 - mean, d2 = v2 - mean, d3 = v3 - mean;
    float q = d0 * d0 + d1 * d1 + d2 * d2 + d3 * d3;
#pragma unroll
    for (int o = 16; o >= 1; o >>= 1) q += __shfl_xor_sync(0xffffffffu, q, o);
    float r = rsqrtf(q * (1.0f / 128.0f) + LN_EPS);

    float4 g4  = __ldg((const float4*)gamma + lane);
    float4 be4 = __ldg((const float4*)beta + lane);
    float o0 = d0 * r * g4.x + be4.x;
    float o1 = d1 * r * g4.y + be4.y;
    float o2 = d2 * r * g4.z + be4.z;
    float o3 = d3 * r * g4.w + be4.w;
    o0 = o0 > 0.f ? o0 : (expf(o0) - 1.0f);
    o1 = o1 > 0.f ? o1 : (expf(o1) - 1.0f);
    o2 = o2 > 0.f ? o2 : (expf(o2) - 1.0f);
    o3 = o3 > 0.f ? o3 : (expf(o3) - 1.0f);

    *(float4*)(out + (size_t)n * HC + lane * 4) = make_float4(o0, o1, o2, o3);
}

// ---------------------------------------------------------------------------
extern "C" void kernel_launch(void* const* d_in, const int* in_sizes, int n_in,
                              void* d_out, int out_size) {
    const float* x       = (const float*)d_in[0];
    const int*   ei      = (const int*)d_in[1];
    const float* W       = (const float*)d_in[2];
    const float* att_src = (const float*)d_in[3];
    const float* att_dst = (const float*)d_in[4];
    const float* bias    = (const float*)d_in[5];
    const float* gamma   = (const float*)d_in[6];
    const float* beta    = (const float*)d_in[7];
    float*       out     = (float*)d_out;

    const int NB_SCAN1 = (N_NODES + 1023) / 1024;  // 49

    // CSR build (independent of gemm; interleave so it hides behind gemm queue)
    zero_k<<<(N_NODES + 255) / 256, 256>>>();
    hist_k<<<(N_EDGES + 255) / 256, 256>>>(ei);
    gemm_mma_k<<<(N_NODES + 127) / 128, 256>>>(x, W, att_src, att_dst);
    scan1_k<<<NB_SCAN1, 1024>>>();
    scan2_k<<<1, 64>>>(NB_SCAN1);
    scan3_k<<<(N_NODES + 255) / 256, 256>>>();
    fill_k<<<(N_EDGES + 255) / 256, 256>>>(ei);
    aggr_k<<<(N_NODES * 32 + 255) / 256, 256>>>(bias, gamma, beta, out);
}

// round 5
// speedup vs baseline: 1.7868x; 1.3979x over previous
#include <cuda_runtime.h>
#include <cuda_bf16.h>
#include <cstdint>

#define N_NODES 50000
#define N_EDGES 800000
#define IN_DIM  256
#define HC      128   // HEADS * OUT_DIM
#define HEADS   4
#define NEG_SLOPE 0.2f
#define LN_EPS  1e-5f

// Scratch (static device globals; no allocation at runtime)
__device__ float g_h[(size_t)N_NODES * HC];      // transformed features [N,128]
__device__ float g_as[N_NODES * HEADS];          // alpha_src per node/head
__device__ float g_ad[N_NODES * HEADS];          // alpha_dst per node/head
// W pre-split (bf16 hi/lo), transposed to [n][k]
__device__ __nv_bfloat16 g_Whi[HC * IN_DIM];
__device__ __nv_bfloat16 g_Wlo[HC * IN_DIM];
// CSR-by-dst scratch
__device__ int   g_deg[N_NODES];
__device__ int   g_cur[N_NODES];
__device__ int   g_row[N_NODES + 1];
__device__ int   g_col[N_EDGES];
__device__ int   g_scan[50176];
__device__ int   g_poff[64];

// ---------------------------------------------------------------------------
// W prepass: split into bf16 hi/lo, transpose [K][N] -> [n][k]
// ---------------------------------------------------------------------------
__global__ __launch_bounds__(256) void splitw_k(const float* __restrict__ W) {
    int i = blockIdx.x * 256 + threadIdx.x;           // 32768 elems
    if (i >= IN_DIM * HC) return;
    int k = i >> 7, n = i & 127;
    float v = W[i];
    __nv_bfloat16 h = __float2bfloat16(v);
    float r = v - __bfloat162float(h);
    g_Whi[n * IN_DIM + k] = h;
    g_Wlo[n * IN_DIM + k] = __float2bfloat16(r);
}

#define MMA_BF16(D, A0, A1, A2, A3, B0, B1)                                   \
    asm volatile(                                                             \
        "mma.sync.aligned.m16n8k16.row.col.f32.bf16.bf16.f32 "                \
        "{%0,%1,%2,%3},{%4,%5,%6,%7},{%8,%9},{%0,%1,%2,%3};"                  \
        : "+f"(D[0]), "+f"(D[1]), "+f"(D[2]), "+f"(D[3])                      \
        : "r"(A0), "r"(A1), "r"(A2), "r"(A3), "r"(B0), "r"(B1))

// ---------------------------------------------------------------------------
// K1: h = x@W via 3-term bf16-split mma (xh*wh + xh*wl + xl*wh), fused with
// attention logits. Block: 256 thr = 8 warps; block tile M=128,N=128,K-chunk 32.
// Warp tile: M=32 (2 m16), N=64 (8 n8). warp_m = wid&3, warp_n = wid>>2.
// Smem rows padded to 40 bf16 (20 words) -> conflict-free fragment LDS.
// ---------------------------------------------------------------------------
__global__ __launch_bounds__(256, 2) void gemm_mma_k(const float* __restrict__ x,
                                                     const float* __restrict__ att_src,
                                                     const float* __restrict__ att_dst) {
    __shared__ __nv_bfloat16 Xh[128][40], Xl[128][40];
    __shared__ __nv_bfloat16 Wh[128][40], Wl[128][40];   // [n][k_local]

    const int tid  = threadIdx.x;
    const int wid  = tid >> 5;
    const int lane = tid & 31;
    const int g    = lane >> 2;     // group row
    const int tig  = lane & 3;      // thread in group
    const int wm   = (wid & 3) * 32;
    const int wn   = (wid >> 2) * 64;
    const int nb   = blockIdx.x * 128;

    float d[2][8][4];
#pragma unroll
    for (int mt = 0; mt < 2; mt++)
#pragma unroll
        for (int nt = 0; nt < 8; nt++)
#pragma unroll
            for (int c = 0; c < 4; c++) d[mt][nt][c] = 0.f;

    for (int kc = 0; kc < IN_DIM; kc += 32) {
        // --- X chunk: 128 rows x 32 k, split to bf16 hi/lo ---
#pragma unroll
        for (int i = 0; i < 4; i++) {
            int idx = tid + i * 256;           // 0..1023
            int row = idx >> 3, q = idx & 7;   // q: float4 within 32 k
            int gn  = nb + row; if (gn > N_NODES - 1) gn = N_NODES - 1;
            float4 v = *(const float4*)(x + (size_t)gn * IN_DIM + kc + q * 4);
            __nv_bfloat162 h01 = make_bfloat162(__float2bfloat16(v.x), __float2bfloat16(v.y));
            __nv_bfloat162 h23 = make_bfloat162(__float2bfloat16(v.z), __float2bfloat16(v.w));
            __nv_bfloat162 l01 = make_bfloat162(
                __float2bfloat16(v.x - __bfloat162float(h01.x)),
                __float2bfloat16(v.y - __bfloat162float(h01.y)));
            __nv_bfloat162 l23 = make_bfloat162(
                __float2bfloat16(v.z - __bfloat162float(h23.x)),
                __float2bfloat16(v.w - __bfloat162float(h23.y)));
            *(__nv_bfloat162*)&Xh[row][q * 4]     = h01;
            *(__nv_bfloat162*)&Xh[row][q * 4 + 2] = h23;
            *(__nv_bfloat162*)&Xl[row][q * 4]     = l01;
            *(__nv_bfloat162*)&Xl[row][q * 4 + 2] = l23;
        }
        // --- W chunk: 128 n-rows x 32 k (pre-split bf16, straight copy) ---
#pragma unroll
        for (int i = 0; i < 2; i++) {
            int idx = tid + i * 256;           // 0..511
            int n = idx >> 2, q = idx & 3;     // q: 8-bf16 unit within 32 k
            *(uint4*)&Wh[n][q * 8] = *(const uint4*)(g_Whi + (size_t)n * IN_DIM + kc + q * 8);
            *(uint4*)&Wl[n][q * 8] = *(const uint4*)(g_Wlo + (size_t)n * IN_DIM + kc + q * 8);
        }
        __syncthreads();

#pragma unroll
        for (int ks = 0; ks < 32; ks += 16) {
            uint32_t ah[2][4], al[2][4];
#pragma unroll
            for (int mt = 0; mt < 2; mt++) {
                int r0 = wm + mt * 16 + g;
                ah[mt][0] = *(const uint32_t*)&Xh[r0    ][ks + 2 * tig];
                ah[mt][1] = *(const uint32_t*)&Xh[r0 + 8][ks + 2 * tig];
                ah[mt][2] = *(const uint32_t*)&Xh[r0    ][ks + 2 * tig + 8];
                ah[mt][3] = *(const uint32_t*)&Xh[r0 + 8][ks + 2 * tig + 8];
                al[mt][0] = *(const uint32_t*)&Xl[r0    ][ks + 2 * tig];
                al[mt][1] = *(const uint32_t*)&Xl[r0 + 8][ks + 2 * tig];
                al[mt][2] = *(const uint32_t*)&Xl[r0    ][ks + 2 * tig + 8];
                al[mt][3] = *(const uint32_t*)&Xl[r0 + 8][ks + 2 * tig + 8];
            }
#pragma unroll
            for (int nt = 0; nt < 8; nt++) {
                int n = wn + nt * 8 + g;
                uint32_t bh0 = *(const uint32_t*)&Wh[n][ks + 2 * tig];
                uint32_t bh1 = *(const uint32_t*)&Wh[n][ks + 2 * tig + 8];
                uint32_t bl0 = *(const uint32_t*)&Wl[n][ks + 2 * tig];
                uint32_t bl1 = *(const uint32_t*)&Wl[n][ks + 2 * tig + 8];
#pragma unroll
                for (int mt = 0; mt < 2; mt++) {
                    MMA_BF16(d[mt][nt], ah[mt][0], ah[mt][1], ah[mt][2], ah[mt][3], bh0, bh1);
                    MMA_BF16(d[mt][nt], ah[mt][0], ah[mt][1], ah[mt][2], ah[mt][3], bl0, bl1);
                    MMA_BF16(d[mt][nt], al[mt][0], al[mt][1], al[mt][2], al[mt][3], bh0, bh1);
                }
            }
        }
        __syncthreads();
    }

    // ---- epilogue: store h + attention logits ----
    // Thread holds rows n0=nb+wm+mt*16+g, n1=n0+8; cols wn+nt*8+2tig(+1).
    // This warp's 64 cols = heads head0, head0+1 (head = col>>5).
    const int head0 = wn >> 5;
    float psl[2][2], pdl[2][2], psh[2][2], pdh[2][2];  // [mt][head-in-warp]
#pragma unroll
    for (int mt = 0; mt < 2; mt++)
#pragma unroll
        for (int hh = 0; hh < 2; hh++) { psl[mt][hh]=pdl[mt][hh]=psh[mt][hh]=pdh[mt][hh]=0.f; }

#pragma unroll
    for (int nt = 0; nt < 8; nt++) {
        int c0 = wn + nt * 8 + 2 * tig;
        int hh = nt >> 2;
        float as0 = __ldg(att_src + c0), as1 = __ldg(att_src + c0 + 1);
        float ad0 = __ldg(att_dst + c0), ad1 = __ldg(att_dst + c0 + 1);
#pragma unroll
        for (int mt = 0; mt < 2; mt++) {
            psl[mt][hh] += d[mt][nt][0] * as0 + d[mt][nt][1] * as1;
            pdl[mt][hh] += d[mt][nt][0] * ad0 + d[mt][nt][1] * ad1;
            psh[mt][hh] += d[mt][nt][2] * as0 + d[mt][nt][3] * as1;
            pdh[mt][hh] += d[mt][nt][2] * ad0 + d[mt][nt][3] * ad1;
        }
    }
#pragma unroll
    for (int mt = 0; mt < 2; mt++)
#pragma unroll
        for (int hh = 0; hh < 2; hh++)
#pragma unroll
            for (int o = 1; o <= 2; o <<= 1) {
                psl[mt][hh] += __shfl_xor_sync(0xffffffffu, psl[mt][hh], o);
                pdl[mt][hh] += __shfl_xor_sync(0xffffffffu, pdl[mt][hh], o);
                psh[mt][hh] += __shfl_xor_sync(0xffffffffu, psh[mt][hh], o);
                pdh[mt][hh] += __shfl_xor_sync(0xffffffffu, pdh[mt][hh], o);
            }

#pragma unroll
    for (int mt = 0; mt < 2; mt++) {
        int n0 = nb + wm + mt * 16 + g;
        int n1 = n0 + 8;
        if (n0 < N_NODES) {
#pragma unroll
            for (int nt = 0; nt < 8; nt++)
                *(float2*)(g_h + (size_t)n0 * HC + wn + nt * 8 + 2 * tig) =
                    make_float2(d[mt][nt][0], d[mt][nt][1]);
            if (tig == 0)
#pragma unroll
                for (int hh = 0; hh < 2; hh++) {
                    g_as[n0 * HEADS + head0 + hh] = psl[mt][hh];
                    g_ad[n0 * HEADS + head0 + hh] = pdl[mt][hh];
                }
        }
        if (n1 < N_NODES) {
#pragma unroll
            for (int nt = 0; nt < 8; nt++)
                *(float2*)(g_h + (size_t)n1 * HC + wn + nt * 8 + 2 * tig) =
                    make_float2(d[mt][nt][2], d[mt][nt][3]);
            if (tig == 0)
#pragma unroll
                for (int hh = 0; hh < 2; hh++) {
                    g_as[n1 * HEADS + head0 + hh] = psh[mt][hh];
                    g_ad[n1 * HEADS + head0 + hh] = pdh[mt][hh];
                }
        }
    }
}

// ---------------------------------------------------------------------------
// CSR build: zero -> hist -> scan (2-level) -> fill
// ---------------------------------------------------------------------------
__global__ __launch_bounds__(256) void zero_k() {
    int i = blockIdx.x * 256 + threadIdx.x;
    if (i < N_NODES) { g_deg[i] = 0; g_cur[i] = 0; }
}

__global__ __launch_bounds__(256) void hist_k(const int* __restrict__ ei) {
    int e = blockIdx.x * 256 + threadIdx.x;
    if (e < N_EDGES) atomicAdd(&g_deg[__ldg(ei + N_EDGES + e)], 1);
}

__global__ __launch_bounds__(1024) void scan1_k() {
    __shared__ int s[1024];
    int tid = threadIdx.x;
    int i   = blockIdx.x * 1024 + tid;
    int v   = (i < N_NODES) ? g_deg[i] : 0;
    s[tid] = v;
    __syncthreads();
#pragma unroll
    for (int off = 1; off < 1024; off <<= 1) {
        int t = (tid >= off) ? s[tid - off] : 0;
        __syncthreads();
        s[tid] += t;
        __syncthreads();
    }
    g_scan[i] = s[tid];
    if (tid == 1023) g_poff[blockIdx.x] = s[1023];
}

__global__ __launch_bounds__(64) void scan2_k(int nblk) {
    __shared__ int s[64];
    int tid = threadIdx.x;
    s[tid] = (tid < nblk) ? g_poff[tid] : 0;
    __syncthreads();
    if (tid == 0) {
        int run = 0;
        for (int b = 0; b < nblk; b++) { int t = s[b]; s[b] = run; run += t; }
    }
    __syncthreads();
    if (tid < nblk) g_poff[tid] = s[tid];
}

__global__ __launch_bounds__(256) void scan3_k() {
    int i = blockIdx.x * 256 + threadIdx.x;
    if (i < N_NODES) g_row[i + 1] = g_scan[i] + g_poff[i >> 10];
    if (i == 0) g_row[0] = 0;
}

__global__ __launch_bounds__(256) void fill_k(const int* __restrict__ ei) {
    int e = blockIdx.x * 256 + threadIdx.x;
    if (e >= N_EDGES) return;
    int s = __ldg(ei + e);
    int d = __ldg(ei + N_EDGES + e);
    int pos = g_row[d] + atomicAdd(&g_cur[d], 1);
    g_col[pos] = s;
}

// ---------------------------------------------------------------------------
// Aggregation (gather-only) fused with LayerNorm + ELU.
// One warp per dst node; lane owns 4 channels; head = lane>>3.
// ---------------------------------------------------------------------------
__global__ __launch_bounds__(256) void aggr_k(const float* __restrict__ bias,
                                              const float* __restrict__ gamma,
                                              const float* __restrict__ beta,
                                              float* __restrict__ out) {
    int gt   = blockIdx.x * 256 + threadIdx.x;
    int n    = gt >> 5;
    int lane = gt & 31;
    if (n >= N_NODES) return;
    int head = lane >> 3;

    float ad_n = __ldg(g_ad + n * HEADS + head);

    // self-loop initializes the accumulator
    float as_s = __ldg(g_as + n * HEADS + head);
    float z    = as_s + ad_n;
    float w    = __expf(z > 0.f ? z : NEG_SLOPE * z);
    float4 hv  = __ldg((const float4*)(g_h + (size_t)n * HC) + lane);
    float a0 = w * hv.x, a1 = w * hv.y, a2 = w * hv.z, a3 = w * hv.w;
    float den = w;

    int e0 = __ldg(g_row + n), e1 = __ldg(g_row + n + 1);
    int s_next = (e0 < e1) ? __ldg(g_col + e0) : 0;
    for (int i = e0; i < e1; i++) {
        int s = s_next;
        if (i + 1 < e1) s_next = __ldg(g_col + i + 1);
        float4 h4 = __ldg((const float4*)(g_h + (size_t)s * HC) + lane);
        float as  = __ldg(g_as + s * HEADS + head);
        float zz  = as + ad_n;
        float ww  = __expf(zz > 0.f ? zz : NEG_SLOPE * zz);
        a0 = fmaf(ww, h4.x, a0);
        a1 = fmaf(ww, h4.y, a1);
        a2 = fmaf(ww, h4.z, a2);
        a3 = fmaf(ww, h4.w, a3);
        den += ww;
    }

    float inv = 1.0f / den;
    float4 b4 = __ldg((const float4*)bias + lane);
    float v0 = a0 * inv + b4.x;
    float v1 = a1 * inv + b4.y;
    float v2 = a2 * inv + b4.z;
    float v3 = a3 * inv + b4.w;

    float s = v0 + v1 + v2 + v3;
#pragma unroll
    for (int o = 16; o >= 1; o >>= 1) s += __shfl_xor_sync(0xffffffffu, s, o);
    float mean = s * (1.0f / 128.0f);

    float d0 = v0 - mean, d1 = v1 - mean, d2 = v2 - mean, d3 = v3 - mean;
    float q = d0 * d0 + d1 * d1 + d2 * d2 + d3 * d3;
#pragma unroll
    for (int o = 16; o >= 1; o >>= 1) q += __shfl_xor_sync(0xffffffffu, q, o);
    float r = rsqrtf(q * (1.0f / 128.0f) + LN_EPS);

    float4 g4  = __ldg((const float4*)gamma + lane);
    float4 be4 = __ldg((const float4*)beta + lane);
    float o0 = d0 * r * g4.x + be4.x;
    float o1 = d1 * r * g4.y + be4.y;
    float o2 = d2 * r * g4.z + be4.z;
    float o3 = d3 * r * g4.w + be4.w;
    o0 = o0 > 0.f ? o0 : (expf(o0) - 1.0f);
    o1 = o1 > 0.f ? o1 : (expf(o1) - 1.0f);
    o2 = o2 > 0.f ? o2 : (expf(o2) - 1.0f);
    o3 = o3 > 0.f ? o3 : (expf(o3) - 1.0f);

    *(float4*)(out + (size_t)n * HC + lane * 4) = make_float4(o0, o1, o2, o3);
}

// ---------------------------------------------------------------------------
extern "C" void kernel_launch(void* const* d_in, const int* in_sizes, int n_in,
                              void* d_out, int out_size) {
    const float* x       = (const float*)d_in[0];
    const int*   ei      = (const int*)d_in[1];
    const float* W       = (const float*)d_in[2];
    const float* att_src = (const float*)d_in[3];
    const float* att_dst = (const float*)d_in[4];
    const float* bias    = (const float*)d_in[5];
    const float* gamma   = (const float*)d_in[6];
    const float* beta    = (const float*)d_in[7];
    float*       out     = (float*)d_out;

    const int NB_SCAN1 = (N_NODES + 1023) / 1024;  // 49

    splitw_k<<<(IN_DIM * HC + 255) / 256, 256>>>(W);
    zero_k<<<(N_NODES + 255) / 256, 256>>>();
    hist_k<<<(N_EDGES + 255) / 256, 256>>>(ei);
    gemm_mma_k<<<(N_NODES + 127) / 128, 256>>>(x, att_src, att_dst);
    scan1_k<<<NB_SCAN1, 1024>>>();
    scan2_k<<<1, 64>>>(NB_SCAN1);
    scan3_k<<<(N_NODES + 255) / 256, 256>>>();
    fill_k<<<(N_EDGES + 255) / 256, 256>>>(ei);
    aggr_k<<<(N_NODES * 32 + 255) / 256, 256>>>(bias, gamma, beta, out);
}

// round 6
// speedup vs baseline: 1.9138x; 1.0710x over previous
#include <cuda_runtime.h>
#include <cuda_bf16.h>
#include <cstdint>

#define N_NODES 50000
#define N_EDGES 800000
#define IN_DIM  256
#define HC      128   // HEADS * OUT_DIM
#define HEADS   4
#define NEG_SLOPE 0.2f
#define LN_EPS  1e-5f

// Scratch (static device globals; no allocation at runtime)
__device__ float g_h[(size_t)N_NODES * HC];      // transformed features [N,128]
__device__ float g_as[N_NODES * HEADS];          // alpha_src per node/head
__device__ float g_ad[N_NODES * HEADS];          // alpha_dst per node/head
// W pre-split (bf16 hi/lo), transposed to [n][k]
__device__ __nv_bfloat16 g_Whi[HC * IN_DIM];
__device__ __nv_bfloat16 g_Wlo[HC * IN_DIM];
// CSR-by-dst scratch
__device__ int   g_deg[N_NODES];
__device__ int   g_cur[N_NODES];
__device__ int   g_row[N_NODES + 1];
__device__ int   g_col[N_EDGES];
__device__ int   g_scan[50176];
__device__ int   g_poff[64];

// ---------------------------------------------------------------------------
// Prep: split W into bf16 hi/lo transposed [n][k]; also zero deg/cur.
// ---------------------------------------------------------------------------
__global__ __launch_bounds__(256) void prep_k(const float* __restrict__ W) {
    int i = blockIdx.x * 256 + threadIdx.x;
    if (i < IN_DIM * HC) {
        int k = i >> 7, n = i & 127;
        float v = W[i];
        __nv_bfloat16 h = __float2bfloat16(v);
        float r = v - __bfloat162float(h);
        g_Whi[n * IN_DIM + k] = h;
        g_Wlo[n * IN_DIM + k] = __float2bfloat16(r);
    }
    if (i < N_NODES) { g_deg[i] = 0; g_cur[i] = 0; }
}

#define MMA_BF16(D, A0, A1, A2, A3, B0, B1)                                   \
    asm volatile(                                                             \
        "mma.sync.aligned.m16n8k16.row.col.f32.bf16.bf16.f32 "                \
        "{%0,%1,%2,%3},{%4,%5,%6,%7},{%8,%9},{%0,%1,%2,%3};"                  \
        : "+f"(D[0]), "+f"(D[1]), "+f"(D[2]), "+f"(D[3])                      \
        : "r"(A0), "r"(A1), "r"(A2), "r"(A3), "r"(B0), "r"(B1))

#define CP16(dst_u32, src_ptr)                                                \
    asm volatile("cp.async.cg.shared.global [%0], [%1], 16;" ::               \
                 "r"(dst_u32), "l"(src_ptr))
#define CP_COMMIT() asm volatile("cp.async.commit_group;")
#define CP_WAIT0()  asm volatile("cp.async.wait_group 0;")

// stage layout (bytes): Xh[128][40] | Xl | Wh[128][40] | Wl  = 4*10240
#define STG_BYTES 40960
#define XH_OFF 0
#define XL_OFF 10240
#define WH_OFF 20480
#define WL_OFF 30720

// ---------------------------------------------------------------------------
// K1: h = x@W via 3-term bf16-split mma, double-buffered pipeline.
// Block 256 thr (8 warps); tile M=128,N=128; K-chunk 32; 2 smem stages.
// X staged through registers (LDG early, convert+store late);
// W copied with cp.async (pre-split bf16, straight 16B copies).
// ---------------------------------------------------------------------------
__global__ __launch_bounds__(256, 2) void gemm_mma_k(const float* __restrict__ x,
                                                     const float* __restrict__ att_src,
                                                     const float* __restrict__ att_dst) {
    extern __shared__ __align__(16) char sm_raw[];

    const int tid  = threadIdx.x;
    const int wid  = tid >> 5;
    const int lane = tid & 31;
    const int g    = lane >> 2;
    const int tig  = lane & 3;
    const int wm   = (wid & 3) * 32;
    const int wn   = (wid >> 2) * 64;
    const int nb   = blockIdx.x * 128;

    // per-thread fixed load coordinates
    const float* xsrc[4];
    int xrow[4], xq[4];
#pragma unroll
    for (int i = 0; i < 4; i++) {
        int idx = tid + i * 256;
        int row = idx >> 3, q = idx & 7;
        int gn  = nb + row; if (gn > N_NODES - 1) gn = N_NODES - 1;
        xrow[i] = row; xq[i] = q;
        xsrc[i] = x + (size_t)gn * IN_DIM + q * 4;
    }
    int wrow[2], wq[2];
#pragma unroll
    for (int i = 0; i < 2; i++) {
        int idx = tid + i * 256;
        wrow[i] = idx >> 2; wq[i] = idx & 3;
    }

    float d[2][8][4];
#pragma unroll
    for (int mt = 0; mt < 2; mt++)
#pragma unroll
        for (int nt = 0; nt < 8; nt++)
#pragma unroll
            for (int c = 0; c < 4; c++) d[mt][nt][c] = 0.f;

    float4 xs[4];

    // helpers as macros-in-code
    // --- prologue: chunk 0 ---
    {
        char* st0 = sm_raw;
#pragma unroll
        for (int i = 0; i < 2; i++) {
            uint32_t dh = (uint32_t)__cvta_generic_to_shared(
                st0 + WH_OFF + (wrow[i] * 40 + wq[i] * 8) * 2);
            uint32_t dl = (uint32_t)__cvta_generic_to_shared(
                st0 + WL_OFF + (wrow[i] * 40 + wq[i] * 8) * 2);
            CP16(dh, g_Whi + (size_t)wrow[i] * IN_DIM + wq[i] * 8);
            CP16(dl, g_Wlo + (size_t)wrow[i] * IN_DIM + wq[i] * 8);
        }
        CP_COMMIT();
#pragma unroll
        for (int i = 0; i < 4; i++) xs[i] = *(const float4*)(xsrc[i]);
        __nv_bfloat16* Xh = (__nv_bfloat16*)(st0 + XH_OFF);
        __nv_bfloat16* Xl = (__nv_bfloat16*)(st0 + XL_OFF);
#pragma unroll
        for (int i = 0; i < 4; i++) {
            float4 v = xs[i];
            __nv_bfloat162 h01 = make_bfloat162(__float2bfloat16(v.x), __float2bfloat16(v.y));
            __nv_bfloat162 h23 = make_bfloat162(__float2bfloat16(v.z), __float2bfloat16(v.w));
            __nv_bfloat162 l01 = make_bfloat162(
                __float2bfloat16(v.x - __bfloat162float(h01.x)),
                __float2bfloat16(v.y - __bfloat162float(h01.y)));
            __nv_bfloat162 l23 = make_bfloat162(
                __float2bfloat16(v.z - __bfloat162float(h23.x)),
                __float2bfloat16(v.w - __bfloat162float(h23.y)));
            int o = xrow[i] * 40 + xq[i] * 4;
            *(__nv_bfloat162*)&Xh[o]     = h01;
            *(__nv_bfloat162*)&Xh[o + 2] = h23;
            *(__nv_bfloat162*)&Xl[o]     = l01;
            *(__nv_bfloat162*)&Xl[o + 2] = l23;
        }
        CP_WAIT0();
        __syncthreads();
    }

    for (int c = 0; c < 8; c++) {
        const int cur = c & 1;
        const int nxt = cur ^ 1;
        char* bc = sm_raw + cur * STG_BYTES;
        char* bn = sm_raw + nxt * STG_BYTES;
        const __nv_bfloat16* Xh = (const __nv_bfloat16*)(bc + XH_OFF);
        const __nv_bfloat16* Xl = (const __nv_bfloat16*)(bc + XL_OFF);
        const __nv_bfloat16* Wh = (const __nv_bfloat16*)(bc + WH_OFF);
        const __nv_bfloat16* Wl = (const __nv_bfloat16*)(bc + WL_OFF);

        if (c < 7) {
            const int kc = (c + 1) * 32;
            // prefetch W -> next stage (async), X -> registers
#pragma unroll
            for (int i = 0; i < 2; i++) {
                uint32_t dh = (uint32_t)__cvta_generic_to_shared(
                    bn + WH_OFF + (wrow[i] * 40 + wq[i] * 8) * 2);
                uint32_t dl = (uint32_t)__cvta_generic_to_shared(
                    bn + WL_OFF + (wrow[i] * 40 + wq[i] * 8) * 2);
                CP16(dh, g_Whi + (size_t)wrow[i] * IN_DIM + kc + wq[i] * 8);
                CP16(dl, g_Wlo + (size_t)wrow[i] * IN_DIM + kc + wq[i] * 8);
            }
            CP_COMMIT();
#pragma unroll
            for (int i = 0; i < 4; i++) xs[i] = *(const float4*)(xsrc[i] + kc);
        }

        // --- compute on current stage ---
#pragma unroll
        for (int ks = 0; ks < 32; ks += 16) {
            uint32_t ah[2][4], al[2][4];
#pragma unroll
            for (int mt = 0; mt < 2; mt++) {
                int r0 = (wm + mt * 16 + g) * 40;
                int r1 = r0 + 8 * 40;
                ah[mt][0] = *(const uint32_t*)&Xh[r0 + ks + 2 * tig];
                ah[mt][1] = *(const uint32_t*)&Xh[r1 + ks + 2 * tig];
                ah[mt][2] = *(const uint32_t*)&Xh[r0 + ks + 2 * tig + 8];
                ah[mt][3] = *(const uint32_t*)&Xh[r1 + ks + 2 * tig + 8];
                al[mt][0] = *(const uint32_t*)&Xl[r0 + ks + 2 * tig];
                al[mt][1] = *(const uint32_t*)&Xl[r1 + ks + 2 * tig];
                al[mt][2] = *(const uint32_t*)&Xl[r0 + ks + 2 * tig + 8];
                al[mt][3] = *(const uint32_t*)&Xl[r1 + ks + 2 * tig + 8];
            }
#pragma unroll
            for (int nt = 0; nt < 8; nt++) {
                int n = (wn + nt * 8 + g) * 40;
                uint32_t bh0 = *(const uint32_t*)&Wh[n + ks + 2 * tig];
                uint32_t bh1 = *(const uint32_t*)&Wh[n + ks + 2 * tig + 8];
                uint32_t bl0 = *(const uint32_t*)&Wl[n + ks + 2 * tig];
                uint32_t bl1 = *(const uint32_t*)&Wl[n + ks + 2 * tig + 8];
#pragma unroll
                for (int mt = 0; mt < 2; mt++) {
                    MMA_BF16(d[mt][nt], ah[mt][0], ah[mt][1], ah[mt][2], ah[mt][3], bh0, bh1);
                    MMA_BF16(d[mt][nt], ah[mt][0], ah[mt][1], ah[mt][2], ah[mt][3], bl0, bl1);
                    MMA_BF16(d[mt][nt], al[mt][0], al[mt][1], al[mt][2], al[mt][3], bh0, bh1);
                }
            }
        }

        if (c < 7) {
            // convert + store staged X into next stage
            __nv_bfloat16* Xhn = (__nv_bfloat16*)(bn + XH_OFF);
            __nv_bfloat16* Xln = (__nv_bfloat16*)(bn + XL_OFF);
#pragma unroll
            for (int i = 0; i < 4; i++) {
                float4 v = xs[i];
                __nv_bfloat162 h01 = make_bfloat162(__float2bfloat16(v.x), __float2bfloat16(v.y));
                __nv_bfloat162 h23 = make_bfloat162(__float2bfloat16(v.z), __float2bfloat16(v.w));
                __nv_bfloat162 l01 = make_bfloat162(
                    __float2bfloat16(v.x - __bfloat162float(h01.x)),
                    __float2bfloat16(v.y - __bfloat162float(h01.y)));
                __nv_bfloat162 l23 = make_bfloat162(
                    __float2bfloat16(v.z - __bfloat162float(h23.x)),
                    __float2bfloat16(v.w - __bfloat162float(h23.y)));
                int o = xrow[i] * 40 + xq[i] * 4;
                *(__nv_bfloat162*)&Xhn[o]     = h01;
                *(__nv_bfloat162*)&Xhn[o + 2] = h23;
                *(__nv_bfloat162*)&Xln[o]     = l01;
                *(__nv_bfloat162*)&Xln[o + 2] = l23;
            }
            CP_WAIT0();
        }
        __syncthreads();
    }

    // ---- epilogue: store h + attention logits ----
    const int head0 = wn >> 5;
    float psl[2][2], pdl[2][2], psh[2][2], pdh[2][2];
#pragma unroll
    for (int mt = 0; mt < 2; mt++)
#pragma unroll
        for (int hh = 0; hh < 2; hh++) { psl[mt][hh]=pdl[mt][hh]=psh[mt][hh]=pdh[mt][hh]=0.f; }

#pragma unroll
    for (int nt = 0; nt < 8; nt++) {
        int c0 = wn + nt * 8 + 2 * tig;
        int hh = nt >> 2;
        float as0 = __ldg(att_src + c0), as1 = __ldg(att_src + c0 + 1);
        float ad0 = __ldg(att_dst + c0), ad1 = __ldg(att_dst + c0 + 1);
#pragma unroll
        for (int mt = 0; mt < 2; mt++) {
            psl[mt][hh] += d[mt][nt][0] * as0 + d[mt][nt][1] * as1;
            pdl[mt][hh] += d[mt][nt][0] * ad0 + d[mt][nt][1] * ad1;
            psh[mt][hh] += d[mt][nt][2] * as0 + d[mt][nt][3] * as1;
            pdh[mt][hh] += d[mt][nt][2] * ad0 + d[mt][nt][3] * ad1;
        }
    }
#pragma unroll
    for (int mt = 0; mt < 2; mt++)
#pragma unroll
        for (int hh = 0; hh < 2; hh++)
#pragma unroll
            for (int o = 1; o <= 2; o <<= 1) {
                psl[mt][hh] += __shfl_xor_sync(0xffffffffu, psl[mt][hh], o);
                pdl[mt][hh] += __shfl_xor_sync(0xffffffffu, pdl[mt][hh], o);
                psh[mt][hh] += __shfl_xor_sync(0xffffffffu, psh[mt][hh], o);
                pdh[mt][hh] += __shfl_xor_sync(0xffffffffu, pdh[mt][hh], o);
            }

#pragma unroll
    for (int mt = 0; mt < 2; mt++) {
        int n0 = nb + wm + mt * 16 + g;
        int n1 = n0 + 8;
        if (n0 < N_NODES) {
#pragma unroll
            for (int nt = 0; nt < 8; nt++)
                *(float2*)(g_h + (size_t)n0 * HC + wn + nt * 8 + 2 * tig) =
                    make_float2(d[mt][nt][0], d[mt][nt][1]);
            if (tig == 0)
#pragma unroll
                for (int hh = 0; hh < 2; hh++) {
                    g_as[n0 * HEADS + head0 + hh] = psl[mt][hh];
                    g_ad[n0 * HEADS + head0 + hh] = pdl[mt][hh];
                }
        }
        if (n1 < N_NODES) {
#pragma unroll
            for (int nt = 0; nt < 8; nt++)
                *(float2*)(g_h + (size_t)n1 * HC + wn + nt * 8 + 2 * tig) =
                    make_float2(d[mt][nt][2], d[mt][nt][3]);
            if (tig == 0)
#pragma unroll
                for (int hh = 0; hh < 2; hh++) {
                    g_as[n1 * HEADS + head0 + hh] = psh[mt][hh];
                    g_ad[n1 * HEADS + head0 + hh] = pdh[mt][hh];
                }
        }
    }
}

// ---------------------------------------------------------------------------
// CSR build: hist -> scan (2-level, warp-shuffle) -> fill
// ---------------------------------------------------------------------------
__global__ __launch_bounds__(256) void hist_k(const int* __restrict__ ei) {
    int e = blockIdx.x * 256 + threadIdx.x;
    if (e < N_EDGES) atomicAdd(&g_deg[__ldg(ei + N_EDGES + e)], 1);
}

__global__ __launch_bounds__(1024) void scan1_k() {
    __shared__ int wsum[32];
    int tid = threadIdx.x, lane = tid & 31, wid = tid >> 5;
    int i = blockIdx.x * 1024 + tid;
    int v = (i < N_NODES) ? g_deg[i] : 0;
    int s = v;
#pragma unroll
    for (int o = 1; o < 32; o <<= 1) {
        int t = __shfl_up_sync(0xffffffffu, s, o);
        if (lane >= o) s += t;
    }
    if (lane == 31) wsum[wid] = s;
    __syncthreads();
    if (wid == 0) {
        int t = wsum[lane];
#pragma unroll
        for (int o = 1; o < 32; o <<= 1) {
            int u = __shfl_up_sync(0xffffffffu, t, o);
            if (lane >= o) t += u;
        }
        wsum[lane] = t;
    }
    __syncthreads();
    if (wid > 0) s += wsum[wid - 1];
    g_scan[i] = s;
    if (tid == 1023) g_poff[blockIdx.x] = s;
}

__global__ __launch_bounds__(64) void scan2_k(int nblk) {
    __shared__ int s[64];
    int tid = threadIdx.x;
    s[tid] = (tid < nblk) ? g_poff[tid] : 0;
    __syncthreads();
    if (tid == 0) {
        int run = 0;
        for (int b = 0; b < nblk; b++) { int t = s[b]; s[b] = run; run += t; }
    }
    __syncthreads();
    if (tid < nblk) g_poff[tid] = s[tid];
}

__global__ __launch_bounds__(256) void scan3_k() {
    int i = blockIdx.x * 256 + threadIdx.x;
    if (i < N_NODES) g_row[i + 1] = g_scan[i] + g_poff[i >> 10];
    if (i == 0) g_row[0] = 0;
}

__global__ __launch_bounds__(256) void fill_k(const int* __restrict__ ei) {
    int e = blockIdx.x * 256 + threadIdx.x;
    if (e >= N_EDGES) return;
    int s = __ldg(ei + e);
    int d = __ldg(ei + N_EDGES + e);
    int pos = g_row[d] + atomicAdd(&g_cur[d], 1);
    g_col[pos] = s;
}

// ---------------------------------------------------------------------------
// Aggregation (gather-only) fused with LayerNorm + ELU.
// One warp per dst node; lane owns 4 channels; head = lane>>3.
// ---------------------------------------------------------------------------
__global__ __launch_bounds__(256) void aggr_k(const float* __restrict__ bias,
                                              const float* __restrict__ gamma,
                                              const float* __restrict__ beta,
                                              float* __restrict__ out) {
    int gt   = blockIdx.x * 256 + threadIdx.x;
    int n    = gt >> 5;
    int lane = gt & 31;
    if (n >= N_NODES) return;
    int head = lane >> 3;

    float ad_n = __ldg(g_ad + n * HEADS + head);

    float as_s = __ldg(g_as + n * HEADS + head);
    float z    = as_s + ad_n;
    float w    = __expf(z > 0.f ? z : NEG_SLOPE * z);
    float4 hv  = __ldg((const float4*)(g_h + (size_t)n * HC) + lane);
    float a0 = w * hv.x, a1 = w * hv.y, a2 = w * hv.z, a3 = w * hv.w;
    float den = w;

    int e0 = __ldg(g_row + n), e1 = __ldg(g_row + n + 1);
    int s_next = (e0 < e1) ? __ldg(g_col + e0) : 0;
    for (int i = e0; i < e1; i++) {
        int s = s_next;
        if (i + 1 < e1) s_next = __ldg(g_col + i + 1);
        float4 h4 = __ldg((const float4*)(g_h + (size_t)s * HC) + lane);
        float as  = __ldg(g_as + s * HEADS + head);
        float zz  = as + ad_n;
        float ww  = __expf(zz > 0.f ? zz : NEG_SLOPE * zz);
        a0 = fmaf(ww, h4.x, a0);
        a1 = fmaf(ww, h4.y, a1);
        a2 = fmaf(ww, h4.z, a2);
        a3 = fmaf(ww, h4.w, a3);
        den += ww;
    }

    float inv = 1.0f / den;
    float4 b4 = __ldg((const float4*)bias + lane);
    float v0 = a0 * inv + b4.x;
    float v1 = a1 * inv + b4.y;
    float v2 = a2 * inv + b4.z;
    float v3 = a3 * inv + b4.w;

    float s = v0 + v1 + v2 + v3;
#pragma unroll
    for (int o = 16; o >= 1; o >>= 1) s += __shfl_xor_sync(0xffffffffu, s, o);
    float mean = s * (1.0f / 128.0f);

    float d0 = v0 - mean, d1 = v1 - mean, d2 = v2 - mean, d3 = v3 - mean;
    float q = d0 * d0 + d1 * d1 + d2 * d2 + d3 * d3;
#pragma unroll
    for (int o = 16; o >= 1; o >>= 1) q += __shfl_xor_sync(0xffffffffu, q, o);
    float r = rsqrtf(q * (1.0f / 128.0f) + LN_EPS);

    float4 g4  = __ldg((const float4*)gamma + lane);
    float4 be4 = __ldg((const float4*)beta + lane);
    float o0 = d0 * r * g4.x + be4.x;
    float o1 = d1 * r * g4.y + be4.y;
    float o2 = d2 * r * g4.z + be4.z;
    float o3 = d3 * r * g4.w + be4.w;
    o0 = o0 > 0.f ? o0 : (expf(o0) - 1.0f);
    o1 = o1 > 0.f ? o1 : (expf(o1) - 1.0f);
    o2 = o2 > 0.f ? o2 : (expf(o2) - 1.0f);
    o3 = o3 > 0.f ? o3 : (expf(o3) - 1.0f);

    *(float4*)(out + (size_t)n * HC + lane * 4) = make_float4(o0, o1, o2, o3);
}

// ---------------------------------------------------------------------------
extern "C" void kernel_launch(void* const* d_in, const int* in_sizes, int n_in,
                              void* d_out, int out_size) {
    const float* x       = (const float*)d_in[0];
    const int*   ei      = (const int*)d_in[1];
    const float* W       = (const float*)d_in[2];
    const float* att_src = (const float*)d_in[3];
    const float* att_dst = (const float*)d_in[4];
    const float* bias    = (const float*)d_in[5];
    const float* gamma   = (const float*)d_in[6];
    const float* beta    = (const float*)d_in[7];
    float*       out     = (float*)d_out;

    const int NB_SCAN1 = (N_NODES + 1023) / 1024;  // 49
    const int GEMM_SMEM = 2 * STG_BYTES;           // 80 KB dynamic

    cudaFuncSetAttribute(gemm_mma_k,
                         cudaFuncAttributeMaxDynamicSharedMemorySize, GEMM_SMEM);

    prep_k<<<(N_NODES + 255) / 256, 256>>>(W);     // W split + deg/cur zero
    hist_k<<<(N_EDGES + 255) / 256, 256>>>(ei);
    gemm_mma_k<<<(N_NODES + 127) / 128, 256, GEMM_SMEM>>>(x, att_src, att_dst);
    scan1_k<<<NB_SCAN1, 1024>>>();
    scan2_k<<<1, 64>>>(NB_SCAN1);
    scan3_k<<<(N_NODES + 255) / 256, 256>>>();
    fill_k<<<(N_EDGES + 255) / 256, 256>>>(ei);
    aggr_k<<<(N_NODES * 32 + 255) / 256, 256>>>(bias, gamma, beta, out);
}

// round 7
// speedup vs baseline: 2.1557x; 1.1264x over previous
#include <cuda_runtime.h>
#include <cuda_bf16.h>
#include <cstdint>

#define N_NODES 50000
#define N_EDGES 800000
#define IN_DIM  256
#define HC      128   // HEADS * OUT_DIM
#define HEADS   4
#define NEG_SLOPE 0.2f
#define LN_EPS  1e-5f

// Scratch (static device globals; no allocation at runtime)
__device__ float g_h[(size_t)N_NODES * HC];      // transformed features [N,128]
__device__ float g_as[N_NODES * HEADS];          // alpha_src per node/head
__device__ float g_ad[N_NODES * HEADS];          // alpha_dst per node/head
// W pre-split (bf16 hi/lo), transposed to [n][k]
__device__ __nv_bfloat16 g_Whi[HC * IN_DIM];
__device__ __nv_bfloat16 g_Wlo[HC * IN_DIM];
// CSR-by-dst scratch
__device__ int   g_deg[N_NODES];
__device__ int   g_cur[N_NODES];
__device__ int   g_row[N_NODES + 1];
__device__ int   g_col[N_EDGES];
__device__ int   g_scan[50176];
__device__ int   g_poff[64];

// ---------------------------------------------------------------------------
// Prep (stream 0): split W into bf16 hi/lo transposed [n][k].
// ---------------------------------------------------------------------------
__global__ __launch_bounds__(256) void prep_k(const float* __restrict__ W) {
    int i = blockIdx.x * 256 + threadIdx.x;
    if (i < IN_DIM * HC) {
        int k = i >> 7, n = i & 127;
        float v = W[i];
        __nv_bfloat16 h = __float2bfloat16(v);
        float r = v - __bfloat162float(h);
        g_Whi[n * IN_DIM + k] = h;
        g_Wlo[n * IN_DIM + k] = __float2bfloat16(r);
    }
}

// CSR branch start: zero counters
__global__ __launch_bounds__(256) void zero_k() {
    int i = blockIdx.x * 256 + threadIdx.x;
    if (i < N_NODES) { g_deg[i] = 0; g_cur[i] = 0; }
}

#define MMA_BF16(D, A0, A1, A2, A3, B0, B1)                                   \
    asm volatile(                                                             \
        "mma.sync.aligned.m16n8k16.row.col.f32.bf16.bf16.f32 "                \
        "{%0,%1,%2,%3},{%4,%5,%6,%7},{%8,%9},{%0,%1,%2,%3};"                  \
        : "+f"(D[0]), "+f"(D[1]), "+f"(D[2]), "+f"(D[3])                      \
        : "r"(A0), "r"(A1), "r"(A2), "r"(A3), "r"(B0), "r"(B1))

#define CP16(dst_u32, src_ptr)                                                \
    asm volatile("cp.async.cg.shared.global [%0], [%1], 16;" ::               \
                 "r"(dst_u32), "l"(src_ptr))
#define CP_COMMIT() asm volatile("cp.async.commit_group;")
#define CP_WAIT0()  asm volatile("cp.async.wait_group 0;")

// stage layout (bytes): Xh[128][40] | Xl | Wh[128][40] | Wl  = 4*10240
#define STG_BYTES 40960
#define XH_OFF 0
#define XL_OFF 10240
#define WH_OFF 20480
#define WL_OFF 30720

// ---------------------------------------------------------------------------
// K1: h = x@W via 3-term bf16-split mma, double-buffered pipeline.
// ---------------------------------------------------------------------------
__global__ __launch_bounds__(256, 2) void gemm_mma_k(const float* __restrict__ x,
                                                     const float* __restrict__ att_src,
                                                     const float* __restrict__ att_dst) {
    extern __shared__ __align__(16) char sm_raw[];

    const int tid  = threadIdx.x;
    const int wid  = tid >> 5;
    const int lane = tid & 31;
    const int g    = lane >> 2;
    const int tig  = lane & 3;
    const int wm   = (wid & 3) * 32;
    const int wn   = (wid >> 2) * 64;
    const int nb   = blockIdx.x * 128;

    const float* xsrc[4];
    int xrow[4], xq[4];
#pragma unroll
    for (int i = 0; i < 4; i++) {
        int idx = tid + i * 256;
        int row = idx >> 3, q = idx & 7;
        int gn  = nb + row; if (gn > N_NODES - 1) gn = N_NODES - 1;
        xrow[i] = row; xq[i] = q;
        xsrc[i] = x + (size_t)gn * IN_DIM + q * 4;
    }
    int wrow[2], wq[2];
#pragma unroll
    for (int i = 0; i < 2; i++) {
        int idx = tid + i * 256;
        wrow[i] = idx >> 2; wq[i] = idx & 3;
    }

    float d[2][8][4];
#pragma unroll
    for (int mt = 0; mt < 2; mt++)
#pragma unroll
        for (int nt = 0; nt < 8; nt++)
#pragma unroll
            for (int c = 0; c < 4; c++) d[mt][nt][c] = 0.f;

    float4 xs[4];

    // --- prologue: chunk 0 ---
    {
        char* st0 = sm_raw;
#pragma unroll
        for (int i = 0; i < 2; i++) {
            uint32_t dh = (uint32_t)__cvta_generic_to_shared(
                st0 + WH_OFF + (wrow[i] * 40 + wq[i] * 8) * 2);
            uint32_t dl = (uint32_t)__cvta_generic_to_shared(
                st0 + WL_OFF + (wrow[i] * 40 + wq[i] * 8) * 2);
            CP16(dh, g_Whi + (size_t)wrow[i] * IN_DIM + wq[i] * 8);
            CP16(dl, g_Wlo + (size_t)wrow[i] * IN_DIM + wq[i] * 8);
        }
        CP_COMMIT();
#pragma unroll
        for (int i = 0; i < 4; i++) xs[i] = *(const float4*)(xsrc[i]);
        __nv_bfloat16* Xh = (__nv_bfloat16*)(st0 + XH_OFF);
        __nv_bfloat16* Xl = (__nv_bfloat16*)(st0 + XL_OFF);
#pragma unroll
        for (int i = 0; i < 4; i++) {
            float4 v = xs[i];
            __nv_bfloat162 h01 = make_bfloat162(__float2bfloat16(v.x), __float2bfloat16(v.y));
            __nv_bfloat162 h23 = make_bfloat162(__float2bfloat16(v.z), __float2bfloat16(v.w));
            __nv_bfloat162 l01 = make_bfloat162(
                __float2bfloat16(v.x - __bfloat162float(h01.x)),
                __float2bfloat16(v.y - __bfloat162float(h01.y)));
            __nv_bfloat162 l23 = make_bfloat162(
                __float2bfloat16(v.z - __bfloat162float(h23.x)),
                __float2bfloat16(v.w - __bfloat162float(h23.y)));
            int o = xrow[i] * 40 + xq[i] * 4;
            *(__nv_bfloat162*)&Xh[o]     = h01;
            *(__nv_bfloat162*)&Xh[o + 2] = h23;
            *(__nv_bfloat162*)&Xl[o]     = l01;
            *(__nv_bfloat162*)&Xl[o + 2] = l23;
        }
        CP_WAIT0();
        __syncthreads();
    }

    for (int c = 0; c < 8; c++) {
        const int cur = c & 1;
        const int nxt = cur ^ 1;
        char* bc = sm_raw + cur * STG_BYTES;
        char* bn = sm_raw + nxt * STG_BYTES;
        const __nv_bfloat16* Xh = (const __nv_bfloat16*)(bc + XH_OFF);
        const __nv_bfloat16* Xl = (const __nv_bfloat16*)(bc + XL_OFF);
        const __nv_bfloat16* Wh = (const __nv_bfloat16*)(bc + WH_OFF);
        const __nv_bfloat16* Wl = (const __nv_bfloat16*)(bc + WL_OFF);

        if (c < 7) {
            const int kc = (c + 1) * 32;
#pragma unroll
            for (int i = 0; i < 2; i++) {
                uint32_t dh = (uint32_t)__cvta_generic_to_shared(
                    bn + WH_OFF + (wrow[i] * 40 + wq[i] * 8) * 2);
                uint32_t dl = (uint32_t)__cvta_generic_to_shared(
                    bn + WL_OFF + (wrow[i] * 40 + wq[i] * 8) * 2);
                CP16(dh, g_Whi + (size_t)wrow[i] * IN_DIM + kc + wq[i] * 8);
                CP16(dl, g_Wlo + (size_t)wrow[i] * IN_DIM + kc + wq[i] * 8);
            }
            CP_COMMIT();
#pragma unroll
            for (int i = 0; i < 4; i++) xs[i] = *(const float4*)(xsrc[i] + kc);
        }

#pragma unroll
        for (int ks = 0; ks < 32; ks += 16) {
            uint32_t ah[2][4], al[2][4];
#pragma unroll
            for (int mt = 0; mt < 2; mt++) {
                int r0 = (wm + mt * 16 + g) * 40;
                int r1 = r0 + 8 * 40;
                ah[mt][0] = *(const uint32_t*)&Xh[r0 + ks + 2 * tig];
                ah[mt][1] = *(const uint32_t*)&Xh[r1 + ks + 2 * tig];
                ah[mt][2] = *(const uint32_t*)&Xh[r0 + ks + 2 * tig + 8];
                ah[mt][3] = *(const uint32_t*)&Xh[r1 + ks + 2 * tig + 8];
                al[mt][0] = *(const uint32_t*)&Xl[r0 + ks + 2 * tig];
                al[mt][1] = *(const uint32_t*)&Xl[r1 + ks + 2 * tig];
                al[mt][2] = *(const uint32_t*)&Xl[r0 + ks + 2 * tig + 8];
                al[mt][3] = *(const uint32_t*)&Xl[r1 + ks + 2 * tig + 8];
            }
#pragma unroll
            for (int nt = 0; nt < 8; nt++) {
                int n = (wn + nt * 8 + g) * 40;
                uint32_t bh0 = *(const uint32_t*)&Wh[n + ks + 2 * tig];
                uint32_t bh1 = *(const uint32_t*)&Wh[n + ks + 2 * tig + 8];
                uint32_t bl0 = *(const uint32_t*)&Wl[n + ks + 2 * tig];
                uint32_t bl1 = *(const uint32_t*)&Wl[n + ks + 2 * tig + 8];
#pragma unroll
                for (int mt = 0; mt < 2; mt++) {
                    MMA_BF16(d[mt][nt], ah[mt][0], ah[mt][1], ah[mt][2], ah[mt][3], bh0, bh1);
                    MMA_BF16(d[mt][nt], ah[mt][0], ah[mt][1], ah[mt][2], ah[mt][3], bl0, bl1);
                    MMA_BF16(d[mt][nt], al[mt][0], al[mt][1], al[mt][2], al[mt][3], bh0, bh1);
                }
            }
        }

        if (c < 7) {
            __nv_bfloat16* Xhn = (__nv_bfloat16*)(bn + XH_OFF);
            __nv_bfloat16* Xln = (__nv_bfloat16*)(bn + XL_OFF);
#pragma unroll
            for (int i = 0; i < 4; i++) {
                float4 v = xs[i];
                __nv_bfloat162 h01 = make_bfloat162(__float2bfloat16(v.x), __float2bfloat16(v.y));
                __nv_bfloat162 h23 = make_bfloat162(__float2bfloat16(v.z), __float2bfloat16(v.w));
                __nv_bfloat162 l01 = make_bfloat162(
                    __float2bfloat16(v.x - __bfloat162float(h01.x)),
                    __float2bfloat16(v.y - __bfloat162float(h01.y)));
                __nv_bfloat162 l23 = make_bfloat162(
                    __float2bfloat16(v.z - __bfloat162float(h23.x)),
                    __float2bfloat16(v.w - __bfloat162float(h23.y)));
                int o = xrow[i] * 40 + xq[i] * 4;
                *(__nv_bfloat162*)&Xhn[o]     = h01;
                *(__nv_bfloat162*)&Xhn[o + 2] = h23;
                *(__nv_bfloat162*)&Xln[o]     = l01;
                *(__nv_bfloat162*)&Xln[o + 2] = l23;
            }
            CP_WAIT0();
        }
        __syncthreads();
    }

    // ---- epilogue: store h + attention logits ----
    const int head0 = wn >> 5;
    float psl[2][2], pdl[2][2], psh[2][2], pdh[2][2];
#pragma unroll
    for (int mt = 0; mt < 2; mt++)
#pragma unroll
        for (int hh = 0; hh < 2; hh++) { psl[mt][hh]=pdl[mt][hh]=psh[mt][hh]=pdh[mt][hh]=0.f; }

#pragma unroll
    for (int nt = 0; nt < 8; nt++) {
        int c0 = wn + nt * 8 + 2 * tig;
        int hh = nt >> 2;
        float as0 = __ldg(att_src + c0), as1 = __ldg(att_src + c0 + 1);
        float ad0 = __ldg(att_dst + c0), ad1 = __ldg(att_dst + c0 + 1);
#pragma unroll
        for (int mt = 0; mt < 2; mt++) {
            psl[mt][hh] += d[mt][nt][0] * as0 + d[mt][nt][1] * as1;
            pdl[mt][hh] += d[mt][nt][0] * ad0 + d[mt][nt][1] * ad1;
            psh[mt][hh] += d[mt][nt][2] * as0 + d[mt][nt][3] * as1;
            pdh[mt][hh] += d[mt][nt][2] * ad0 + d[mt][nt][3] * ad1;
        }
    }
#pragma unroll
    for (int mt = 0; mt < 2; mt++)
#pragma unroll
        for (int hh = 0; hh < 2; hh++)
#pragma unroll
            for (int o = 1; o <= 2; o <<= 1) {
                psl[mt][hh] += __shfl_xor_sync(0xffffffffu, psl[mt][hh], o);
                pdl[mt][hh] += __shfl_xor_sync(0xffffffffu, pdl[mt][hh], o);
                psh[mt][hh] += __shfl_xor_sync(0xffffffffu, psh[mt][hh], o);
                pdh[mt][hh] += __shfl_xor_sync(0xffffffffu, pdh[mt][hh], o);
            }

#pragma unroll
    for (int mt = 0; mt < 2; mt++) {
        int n0 = nb + wm + mt * 16 + g;
        int n1 = n0 + 8;
        if (n0 < N_NODES) {
#pragma unroll
            for (int nt = 0; nt < 8; nt++)
                *(float2*)(g_h + (size_t)n0 * HC + wn + nt * 8 + 2 * tig) =
                    make_float2(d[mt][nt][0], d[mt][nt][1]);
            if (tig == 0)
#pragma unroll
                for (int hh = 0; hh < 2; hh++) {
                    g_as[n0 * HEADS + head0 + hh] = psl[mt][hh];
                    g_ad[n0 * HEADS + head0 + hh] = pdl[mt][hh];
                }
        }
        if (n1 < N_NODES) {
#pragma unroll
            for (int nt = 0; nt < 8; nt++)
                *(float2*)(g_h + (size_t)n1 * HC + wn + nt * 8 + 2 * tig) =
                    make_float2(d[mt][nt][2], d[mt][nt][3]);
            if (tig == 0)
#pragma unroll
                for (int hh = 0; hh < 2; hh++) {
                    g_as[n1 * HEADS + head0 + hh] = psh[mt][hh];
                    g_ad[n1 * HEADS + head0 + hh] = pdh[mt][hh];
                }
        }
    }
}

// ---------------------------------------------------------------------------
// CSR build: hist -> scan (2-level, warp-shuffle) -> fill
// ---------------------------------------------------------------------------
__global__ __launch_bounds__(256) void hist_k(const int* __restrict__ ei) {
    int e = blockIdx.x * 256 + threadIdx.x;
    if (e < N_EDGES) atomicAdd(&g_deg[__ldg(ei + N_EDGES + e)], 1);
}

__global__ __launch_bounds__(1024) void scan1_k() {
    __shared__ int wsum[32];
    int tid = threadIdx.x, lane = tid & 31, wid = tid >> 5;
    int i = blockIdx.x * 1024 + tid;
    int v = (i < N_NODES) ? g_deg[i] : 0;
    int s = v;
#pragma unroll
    for (int o = 1; o < 32; o <<= 1) {
        int t = __shfl_up_sync(0xffffffffu, s, o);
        if (lane >= o) s += t;
    }
    if (lane == 31) wsum[wid] = s;
    __syncthreads();
    if (wid == 0) {
        int t = wsum[lane];
#pragma unroll
        for (int o = 1; o < 32; o <<= 1) {
            int u = __shfl_up_sync(0xffffffffu, t, o);
            if (lane >= o) t += u;
        }
        wsum[lane] = t;
    }
    __syncthreads();
    if (wid > 0) s += wsum[wid - 1];
    g_scan[i] = s;
    if (tid == 1023) g_poff[blockIdx.x] = s;
}

__global__ __launch_bounds__(64) void scan2_k(int nblk) {
    __shared__ int s[64];
    int tid = threadIdx.x;
    s[tid] = (tid < nblk) ? g_poff[tid] : 0;
    __syncthreads();
    if (tid == 0) {
        int run = 0;
        for (int b = 0; b < nblk; b++) { int t = s[b]; s[b] = run; run += t; }
    }
    __syncthreads();
    if (tid < nblk) g_poff[tid] = s[tid];
}

__global__ __launch_bounds__(256) void scan3_k() {
    int i = blockIdx.x * 256 + threadIdx.x;
    if (i < N_NODES) g_row[i + 1] = g_scan[i] + g_poff[i >> 10];
    if (i == 0) g_row[0] = 0;
}

__global__ __launch_bounds__(256) void fill_k(const int* __restrict__ ei) {
    int e = blockIdx.x * 256 + threadIdx.x;
    if (e >= N_EDGES) return;
    int s = __ldg(ei + e);
    int d = __ldg(ei + N_EDGES + e);
    int pos = g_row[d] + atomicAdd(&g_cur[d], 1);
    g_col[pos] = s;
}

// ---------------------------------------------------------------------------
// Aggregation (gather-only) fused with LayerNorm + ELU.
// ---------------------------------------------------------------------------
__global__ __launch_bounds__(256) void aggr_k(const float* __restrict__ bias,
                                              const float* __restrict__ gamma,
                                              const float* __restrict__ beta,
                                              float* __restrict__ out) {
    int gt   = blockIdx.x * 256 + threadIdx.x;
    int n    = gt >> 5;
    int lane = gt & 31;
    if (n >= N_NODES) return;
    int head = lane >> 3;

    float ad_n = __ldg(g_ad + n * HEADS + head);

    float as_s = __ldg(g_as + n * HEADS + head);
    float z    = as_s + ad_n;
    float w    = __expf(z > 0.f ? z : NEG_SLOPE * z);
    float4 hv  = __ldg((const float4*)(g_h + (size_t)n * HC) + lane);
    float a0 = w * hv.x, a1 = w * hv.y, a2 = w * hv.z, a3 = w * hv.w;
    float den = w;

    int e0 = __ldg(g_row + n), e1 = __ldg(g_row + n + 1);
    int s_next = (e0 < e1) ? __ldg(g_col + e0) : 0;
    for (int i = e0; i < e1; i++) {
        int s = s_next;
        if (i + 1 < e1) s_next = __ldg(g_col + i + 1);
        float4 h4 = __ldg((const float4*)(g_h + (size_t)s * HC) + lane);
        float as  = __ldg(g_as + s * HEADS + head);
        float zz  = as + ad_n;
        float ww  = __expf(zz > 0.f ? zz : NEG_SLOPE * zz);
        a0 = fmaf(ww, h4.x, a0);
        a1 = fmaf(ww, h4.y, a1);
        a2 = fmaf(ww, h4.z, a2);
        a3 = fmaf(ww, h4.w, a3);
        den += ww;
    }

    float inv = 1.0f / den;
    float4 b4 = __ldg((const float4*)bias + lane);
    float v0 = a0 * inv + b4.x;
    float v1 = a1 * inv + b4.y;
    float v2 = a2 * inv + b4.z;
    float v3 = a3 * inv + b4.w;

    float s = v0 + v1 + v2 + v3;
#pragma unroll
    for (int o = 16; o >= 1; o >>= 1) s += __shfl_xor_sync(0xffffffffu, s, o);
    float mean = s * (1.0f / 128.0f);

    float d0 = v0 - mean, d1 = v1 - mean, d2 = v2 - mean, d3 = v3 - mean;
    float q = d0 * d0 + d1 * d1 + d2 * d2 + d3 * d3;
#pragma unroll
    for (int o = 16; o >= 1; o >>= 1) q += __shfl_xor_sync(0xffffffffu, q, o);
    float r = rsqrtf(q * (1.0f / 128.0f) + LN_EPS);

    float4 g4  = __ldg((const float4*)gamma + lane);
    float4 be4 = __ldg((const float4*)beta + lane);
    float o0 = d0 * r * g4.x + be4.x;
    float o1 = d1 * r * g4.y + be4.y;
    float o2 = d2 * r * g4.z + be4.z;
    float o3 = d3 * r * g4.w + be4.w;
    o0 = o0 > 0.f ? o0 : (expf(o0) - 1.0f);
    o1 = o1 > 0.f ? o1 : (expf(o1) - 1.0f);
    o2 = o2 > 0.f ? o2 : (expf(o2) - 1.0f);
    o3 = o3 > 0.f ? o3 : (expf(o3) - 1.0f);

    *(float4*)(out + (size_t)n * HC + lane * 4) = make_float4(o0, o1, o2, o3);
}

// ---------------------------------------------------------------------------
// Launch: fork the capture stream so the CSR build (edge_index only) runs
// concurrently with prep+gemm (x, W only); join before aggr.
// ---------------------------------------------------------------------------
extern "C" void kernel_launch(void* const* d_in, const int* in_sizes, int n_in,
                              void* d_out, int out_size) {
    const float* x       = (const float*)d_in[0];
    const int*   ei      = (const int*)d_in[1];
    const float* W       = (const float*)d_in[2];
    const float* att_src = (const float*)d_in[3];
    const float* att_dst = (const float*)d_in[4];
    const float* bias    = (const float*)d_in[5];
    const float* gamma   = (const float*)d_in[6];
    const float* beta    = (const float*)d_in[7];
    float*       out     = (float*)d_out;

    const int NB_SCAN1  = (N_NODES + 1023) / 1024;  // 49
    const int GEMM_SMEM = 2 * STG_BYTES;            // 80 KB dynamic

    cudaFuncSetAttribute(gemm_mma_k,
                         cudaFuncAttributeMaxDynamicSharedMemorySize, GEMM_SMEM);

    // fork: s2 carries the CSR build. Created fresh each call (host objects
    // only; no device allocation). Not destroyed — capture forbids it and
    // kernel_launch is invoked only a handful of times.
    cudaStream_t s2;
    cudaStreamCreateWithFlags(&s2, cudaStreamNonBlocking);
    cudaEvent_t ev_fork, ev_join;
    cudaEventCreateWithFlags(&ev_fork, cudaEventDisableTiming);
    cudaEventCreateWithFlags(&ev_join, cudaEventDisableTiming);

    cudaEventRecord(ev_fork, 0);
    cudaStreamWaitEvent(s2, ev_fork, 0);

    // --- branch A (stream 0): W prep + GEMM/logits ---
    prep_k<<<(IN_DIM * HC + 255) / 256, 256>>>(W);
    gemm_mma_k<<<(N_NODES + 127) / 128, 256, GEMM_SMEM>>>(x, att_src, att_dst);

    // --- branch B (s2): CSR build ---
    zero_k<<<(N_NODES + 255) / 256, 256, 0, s2>>>();
    hist_k<<<(N_EDGES + 255) / 256, 256, 0, s2>>>(ei);
    scan1_k<<<NB_SCAN1, 1024, 0, s2>>>();
    scan2_k<<<1, 64, 0, s2>>>(NB_SCAN1);
    scan3_k<<<(N_NODES + 255) / 256, 256, 0, s2>>>();
    fill_k<<<(N_EDGES + 255) / 256, 256, 0, s2>>>(ei);
    cudaEventRecord(ev_join, s2);

    // --- join, then aggregation + LN + ELU ---
    cudaStreamWaitEvent(0, ev_join, 0);
    aggr_k<<<(N_NODES * 32 + 255) / 256, 256>>>(bias, gamma, beta, out);
}